// round 2
// baseline (speedup 1.0000x reference)
#include <cuda_runtime.h>
#include <math.h>

#define Bv 64
#define Tv 2048
#define Hv 512
#define Uv 128
#define SPLIT 16
#define CHUNK (Tv / SPLIT)   // 128

// scratch (allocation-free rule: __device__ globals)
__device__ float g_u[Bv * Hv];              // W_score @ h_t, per batch
__device__ float g_scores[Bv * Tv];         // scores -> softmax weights (in place)
__device__ float g_part[Bv * SPLIT * Hv];   // partial context sums

// ---------------------------------------------------------------------------
// Kernel 1: u[b,h] = sum_k W_score[h,k] * h_t[b,k]
// grid=64, block=512 (16 warps, each warp does 32 h-rows)
// ---------------------------------------------------------------------------
__global__ void k_u(const float* __restrict__ hid, const float* __restrict__ Ws) {
    int b = blockIdx.x;
    __shared__ float4 sh[Hv / 4];
    int tid = threadIdx.x;
    const float4* htrow = (const float4*)(hid + ((size_t)b * Tv + (Tv - 1)) * Hv);
    if (tid < Hv / 4) sh[tid] = htrow[tid];
    __syncthreads();

    int warp = tid >> 5, lane = tid & 31;
    for (int i = 0; i < 32; i++) {
        int h = warp * 32 + i;
        const float4* wrow = (const float4*)(Ws + (size_t)h * Hv);
        float s = 0.f;
        #pragma unroll
        for (int j = 0; j < 4; j++) {
            float4 wv = wrow[lane + 32 * j];
            float4 hv = sh[lane + 32 * j];
            s += wv.x * hv.x + wv.y * hv.y + wv.z * hv.z + wv.w * hv.w;
        }
        #pragma unroll
        for (int o = 16; o > 0; o >>= 1) s += __shfl_xor_sync(0xffffffffu, s, o);
        if (lane == 0) g_u[b * Hv + h] = s;
    }
}

// ---------------------------------------------------------------------------
// Kernel 2: score[b,t] = hidden[b,t,:] . u[b,:]
// grid=(T/8, B), block=256 (8 warps, one t per warp)
// ---------------------------------------------------------------------------
__global__ void k_score(const float* __restrict__ hid) {
    int b = blockIdx.y;
    __shared__ float4 su[Hv / 4];
    int tid = threadIdx.x;
    if (tid < Hv / 4) su[tid] = ((const float4*)(g_u + b * Hv))[tid];
    __syncthreads();

    int warp = tid >> 5, lane = tid & 31;
    int t = blockIdx.x * 8 + warp;
    const float4* row = (const float4*)(hid + ((size_t)b * Tv + t) * Hv);
    float s = 0.f;
    #pragma unroll
    for (int j = 0; j < 4; j++) {
        float4 hv = row[lane + 32 * j];
        float4 uv = su[lane + 32 * j];
        s += hv.x * uv.x + hv.y * uv.y + hv.z * uv.z + hv.w * uv.w;
    }
    #pragma unroll
    for (int o = 16; o > 0; o >>= 1) s += __shfl_xor_sync(0xffffffffu, s, o);
    if (lane == 0) g_scores[b * Tv + t] = s;
}

// ---------------------------------------------------------------------------
// Kernel 3: softmax over T per batch, in place in g_scores
// grid=64, block=256 (8 elements/thread)
// ---------------------------------------------------------------------------
__global__ void k_softmax() {
    int b = blockIdx.x, tid = threadIdx.x;
    __shared__ float red[256];
    float loc[8];
    float m = -INFINITY;
    #pragma unroll
    for (int j = 0; j < 8; j++) {
        loc[j] = g_scores[b * Tv + tid + 256 * j];
        m = fmaxf(m, loc[j]);
    }
    red[tid] = m; __syncthreads();
    for (int o = 128; o > 0; o >>= 1) {
        if (tid < o) red[tid] = fmaxf(red[tid], red[tid + o]);
        __syncthreads();
    }
    m = red[0]; __syncthreads();

    float sum = 0.f;
    #pragma unroll
    for (int j = 0; j < 8; j++) {
        loc[j] = __expf(loc[j] - m);
        sum += loc[j];
    }
    red[tid] = sum; __syncthreads();
    for (int o = 128; o > 0; o >>= 1) {
        if (tid < o) red[tid] += red[tid + o];
        __syncthreads();
    }
    float inv = 1.0f / red[0];
    #pragma unroll
    for (int j = 0; j < 8; j++)
        g_scores[b * Tv + tid + 256 * j] = loc[j] * inv;
}

// ---------------------------------------------------------------------------
// Kernel 4: partial context: part[b,s,h] = sum_{t in chunk s} w[b,t]*hidden[b,t,h]
// grid=(SPLIT, B), block=128 (one float4 of h per thread)
// Weights staged in shared first so the hot loop is a pure float4 stream.
// ---------------------------------------------------------------------------
__global__ void k_ctx(const float* __restrict__ hid) {
    int b = blockIdx.y, s = blockIdx.x, tid = threadIdx.x;
    __shared__ float sw[CHUNK];
    if (tid < CHUNK) sw[tid] = g_scores[b * Tv + s * CHUNK + tid];
    __syncthreads();

    const float4* base = (const float4*)(hid + ((size_t)b * Tv + (size_t)s * CHUNK) * Hv);
    float4 acc = make_float4(0.f, 0.f, 0.f, 0.f);
    #pragma unroll 4
    for (int t = 0; t < CHUNK; t++) {
        float w = sw[t];
        float4 hv = base[(size_t)t * (Hv / 4) + tid];
        acc.x += w * hv.x; acc.y += w * hv.y;
        acc.z += w * hv.z; acc.w += w * hv.w;
    }
    ((float4*)(g_part + ((size_t)b * SPLIT + s) * Hv))[tid] = acc;
}

// ---------------------------------------------------------------------------
// Kernel 5: reduce partials, concat with h_t, out = tanh(concat @ W_out)
// grid=64, block=128 (one output unit per thread)
// ---------------------------------------------------------------------------
__global__ void k_out(const float* __restrict__ hid,
                      const float* __restrict__ Wout,
                      float* __restrict__ out) {
    int b = blockIdx.x, tid = threadIdx.x;
    __shared__ float cat[2 * Hv];
    #pragma unroll
    for (int i = 0; i < 4; i++) {
        int h = tid + 128 * i;
        float v = 0.f;
        #pragma unroll
        for (int s = 0; s < SPLIT; s++)
            v += g_part[((size_t)b * SPLIT + s) * Hv + h];
        cat[h] = v;
        cat[Hv + h] = hid[((size_t)b * Tv + (Tv - 1)) * Hv + h];
    }
    __syncthreads();

    float acc = 0.f;
    const float* wcol = Wout + tid;
    #pragma unroll 8
    for (int i = 0; i < 2 * Hv; i++)
        acc += cat[i] * wcol[(size_t)i * Uv];
    out[b * Uv + tid] = tanhf(acc);
}

// ---------------------------------------------------------------------------
extern "C" void kernel_launch(void* const* d_in, const int* in_sizes, int n_in,
                              void* d_out, int out_size) {
    const float* hid  = (const float*)d_in[0];   // (64, 2048, 512)
    const float* Ws   = (const float*)d_in[1];   // (512, 512)
    const float* Wout = (const float*)d_in[2];   // (1024, 128)
    float* out = (float*)d_out;                  // (64, 128)

    k_u<<<Bv, 512>>>(hid, Ws);
    dim3 gs(Tv / 8, Bv);
    k_score<<<gs, 256>>>(hid);
    k_softmax<<<Bv, 256>>>();
    dim3 gc(SPLIT, Bv);
    k_ctx<<<gc, 128>>>(hid);
    k_out<<<Bv, 128>>>(hid, Wout, out);
}

// round 3
// speedup vs baseline: 1.0251x; 1.0251x over previous
#include <cuda_runtime.h>
#include <math.h>

#define Bv 64
#define Tv 2048
#define Hv 512
#define Uv 128
#define SPLIT 16
#define CHUNK (Tv / SPLIT)   // 128 rows per chunk, 256 KB

// scratch (allocation-free rule: __device__ globals)
__device__ float g_u[Bv * Hv];              // W_score @ h_t, per batch
__device__ float g_part[Bv * SPLIT * Hv];   // unnormalized partial contexts
__device__ float g_m[Bv * SPLIT];           // per-chunk score max
__device__ float g_z[Bv * SPLIT];           // per-chunk exp-sum (local-max ref)

// ---------------------------------------------------------------------------
// Kernel 1: u[b,h] = sum_k W_score[h,k] * h_t[b,k]
// grid=(4, B) = 256 blocks, block=256 (8 warps x 16 rows each)
// ---------------------------------------------------------------------------
__global__ void k_u(const float* __restrict__ hid, const float* __restrict__ Ws) {
    int b = blockIdx.y, seg = blockIdx.x, tid = threadIdx.x;
    __shared__ float4 sh[Hv / 4];
    const float4* htrow = (const float4*)(hid + ((size_t)b * Tv + (Tv - 1)) * Hv);
    if (tid < Hv / 4) sh[tid] = htrow[tid];
    __syncthreads();

    int warp = tid >> 5, lane = tid & 31;
    #pragma unroll 4
    for (int i = 0; i < 16; i++) {
        int h = seg * 128 + warp * 16 + i;
        const float4* wrow = (const float4*)(Ws + (size_t)h * Hv);
        float s = 0.f;
        #pragma unroll
        for (int j = 0; j < 4; j++) {
            float4 wv = wrow[lane + 32 * j];
            float4 hv = sh[lane + 32 * j];
            s += wv.x * hv.x + wv.y * hv.y + wv.z * hv.z + wv.w * hv.w;
        }
        #pragma unroll
        for (int o = 16; o > 0; o >>= 1) s += __shfl_xor_sync(0xffffffffu, s, o);
        if (lane == 0) g_u[b * Hv + h] = s;
    }
}

// ---------------------------------------------------------------------------
// Kernel 2 (FUSED): per-(b,chunk) score + local softmax + partial context.
// One DRAM pass; second read of the chunk hits L2.
// grid=(SPLIT, B) = 1024 blocks, block=128 (4 warps)
// ---------------------------------------------------------------------------
__global__ void k_fused(const float* __restrict__ hid) {
    int b = blockIdx.y, s = blockIdx.x, tid = threadIdx.x;
    __shared__ float4 su[Hv / 4];    // u[b]
    __shared__ float ssc[CHUNK];     // scores -> weights
    __shared__ float red[128];

    su[tid] = ((const float4*)(g_u + b * Hv))[tid];
    __syncthreads();

    const float* cbase = hid + ((size_t)b * Tv + (size_t)s * CHUNK) * Hv;
    int warp = tid >> 5, lane = tid & 31;

    // Phase 1: scores, warp-per-row (rows strided by 4 warps)
    #pragma unroll 4
    for (int i = 0; i < 32; i++) {
        int r = warp + 4 * i;
        const float4* row = (const float4*)(cbase + (size_t)r * Hv);
        float sc = 0.f;
        #pragma unroll
        for (int j = 0; j < 4; j++) {
            float4 hv = row[lane + 32 * j];
            float4 uv = su[lane + 32 * j];
            sc += hv.x * uv.x + hv.y * uv.y + hv.z * uv.z + hv.w * uv.w;
        }
        #pragma unroll
        for (int o = 16; o > 0; o >>= 1) sc += __shfl_xor_sync(0xffffffffu, sc, o);
        if (lane == 0) ssc[r] = sc;
    }
    __syncthreads();

    // Phase 2: local max + exp weights + local Z
    float sc = ssc[tid];
    red[tid] = sc; __syncthreads();
    #pragma unroll
    for (int o = 64; o > 0; o >>= 1) {
        if (tid < o) red[tid] = fmaxf(red[tid], red[tid + o]);
        __syncthreads();
    }
    float m = red[0]; __syncthreads();
    float w = __expf(sc - m);
    ssc[tid] = w;               // all reads of old ssc finished before the max sync
    red[tid] = w; __syncthreads();
    #pragma unroll
    for (int o = 64; o > 0; o >>= 1) {
        if (tid < o) red[tid] += red[tid + o];
        __syncthreads();
    }
    if (tid == 0) { g_m[b * SPLIT + s] = m; g_z[b * SPLIT + s] = red[0]; }

    // Phase 3: weighted context over the chunk (re-read hits L2)
    const float4* b4 = (const float4*)cbase;
    float4 acc = make_float4(0.f, 0.f, 0.f, 0.f);
    #pragma unroll 4
    for (int t = 0; t < CHUNK; t++) {
        float wt = ssc[t];
        float4 hv = b4[(size_t)t * (Hv / 4) + tid];
        acc.x += wt * hv.x; acc.y += wt * hv.y;
        acc.z += wt * hv.z; acc.w += wt * hv.w;
    }
    ((float4*)(g_part + ((size_t)b * SPLIT + s) * Hv))[tid] = acc;
}

// ---------------------------------------------------------------------------
// Kernel 3: rescale+combine partials, normalize, concat h_t, tanh GEMV
// grid=64, block=128 (one output unit per thread)
// ---------------------------------------------------------------------------
__global__ void k_out(const float* __restrict__ hid,
                      const float* __restrict__ Wout,
                      float* __restrict__ out) {
    int b = blockIdx.x, tid = threadIdx.x;
    __shared__ float cat[2 * Hv];

    float M = -INFINITY;
    #pragma unroll
    for (int s = 0; s < SPLIT; s++) M = fmaxf(M, g_m[b * SPLIT + s]);
    float f[SPLIT];
    float Z = 0.f;
    #pragma unroll
    for (int s = 0; s < SPLIT; s++) {
        f[s] = __expf(g_m[b * SPLIT + s] - M);
        Z += f[s] * g_z[b * SPLIT + s];
    }
    float invZ = 1.0f / Z;

    #pragma unroll
    for (int i = 0; i < 4; i++) {
        int h = tid + 128 * i;
        float v = 0.f;
        #pragma unroll
        for (int s = 0; s < SPLIT; s++)
            v += f[s] * g_part[((size_t)b * SPLIT + s) * Hv + h];
        cat[h] = v * invZ;
        cat[Hv + h] = hid[((size_t)b * Tv + (Tv - 1)) * Hv + h];
    }
    __syncthreads();

    float acc = 0.f;
    const float* wcol = Wout + tid;
    #pragma unroll 8
    for (int i = 0; i < 2 * Hv; i++)
        acc += cat[i] * wcol[(size_t)i * Uv];
    out[b * Uv + tid] = tanhf(acc);
}

// ---------------------------------------------------------------------------
extern "C" void kernel_launch(void* const* d_in, const int* in_sizes, int n_in,
                              void* d_out, int out_size) {
    const float* hid  = (const float*)d_in[0];   // (64, 2048, 512)
    const float* Ws   = (const float*)d_in[1];   // (512, 512)
    const float* Wout = (const float*)d_in[2];   // (1024, 128)
    float* out = (float*)d_out;                  // (64, 128)

    dim3 gu(4, Bv);
    k_u<<<gu, 256>>>(hid, Ws);
    dim3 gf(SPLIT, Bv);
    k_fused<<<gf, 128>>>(hid);
    k_out<<<Bv, 128>>>(hid, Wout, out);
}

// round 6
// speedup vs baseline: 1.7955x; 1.7514x over previous
#include <cuda_runtime.h>
#include <math.h>

#define Bv 64
#define Tv 2048
#define Hv 512
#define Uv 128
#define NBLK 8                 // fused blocks per batch
#define WPB 8                  // warps per fused block
#define NSPLIT (NBLK * WPB)    // 64 warp-splits per batch
#define ROWS_PER_WARP (Tv / NSPLIT)  // 32

// scratch (allocation-free rule: __device__ globals)
__device__ float g_u[Bv * Hv];                   // W_score @ h_t
__device__ float g_part[Bv * NSPLIT * Hv];       // per-warp unnormalized contexts
__device__ float g_m[Bv * NSPLIT];               // per-warp running max
__device__ float g_z[Bv * NSPLIT];               // per-warp exp-sum

// ---------------------------------------------------------------------------
// Kernel 1: u[b,h] = sum_k W_score[h,k] * h_t[b,k]
// grid=(16, B) = 1024 blocks, block=128 (4 warps x 8 rows each)
// ---------------------------------------------------------------------------
__global__ void k_u(const float* __restrict__ hid, const float* __restrict__ Ws) {
    int b = blockIdx.y, seg = blockIdx.x, tid = threadIdx.x;
    __shared__ float4 sh[Hv / 4];
    const float4* htrow = (const float4*)(hid + ((size_t)b * Tv + (Tv - 1)) * Hv);
    sh[tid] = htrow[tid];
    __syncthreads();

    int warp = tid >> 5, lane = tid & 31;
    #pragma unroll
    for (int i = 0; i < 8; i++) {
        int h = seg * 32 + warp * 8 + i;
        const float4* wrow = (const float4*)(Ws + (size_t)h * Hv);
        float s = 0.f;
        #pragma unroll
        for (int j = 0; j < 4; j++) {
            float4 wv = wrow[lane + 32 * j];
            float4 hv = sh[lane + 32 * j];
            s += wv.x * hv.x + wv.y * hv.y + wv.z * hv.z + wv.w * hv.w;
        }
        #pragma unroll
        for (int o = 16; o > 0; o >>= 1) s += __shfl_xor_sync(0xffffffffu, s, o);
        if (lane == 0) g_u[b * Hv + h] = s;
    }
}

// ---------------------------------------------------------------------------
// Kernel 2: single-pass warp-local online softmax + context accumulation.
// Each warp owns 32 rows; row data stays in registers between score and
// accumulation. grid=(NBLK, B)=512 blocks, block=256 (8 warps).
// ---------------------------------------------------------------------------
__global__ void __launch_bounds__(256) k_fused(const float* __restrict__ hid) {
    int b = blockIdx.y, tid = threadIdx.x;
    int warp = tid >> 5, lane = tid & 31;
    __shared__ float4 su[Hv / 4];
    if (tid < Hv / 4) su[tid] = ((const float4*)(g_u + b * Hv))[tid];
    __syncthreads();

    float4 u0 = su[lane], u1 = su[lane + 32], u2 = su[lane + 64], u3 = su[lane + 96];

    int t0 = blockIdx.x * (WPB * ROWS_PER_WARP) + warp * ROWS_PER_WARP;
    const float4* base = (const float4*)(hid + ((size_t)b * Tv + t0) * Hv);

    float m = -INFINITY, Z = 0.f;
    float4 a0 = make_float4(0.f,0.f,0.f,0.f), a1 = a0, a2 = a0, a3 = a0;

    #pragma unroll 4
    for (int t = 0; t < ROWS_PER_WARP; t++) {
        const float4* row = base + (size_t)t * (Hv / 4);
        float4 h0 = row[lane], h1 = row[lane + 32], h2 = row[lane + 64], h3 = row[lane + 96];

        float sc = h0.x*u0.x + h0.y*u0.y + h0.z*u0.z + h0.w*u0.w
                 + h1.x*u1.x + h1.y*u1.y + h1.z*u1.z + h1.w*u1.w
                 + h2.x*u2.x + h2.y*u2.y + h2.z*u2.z + h2.w*u2.w
                 + h3.x*u3.x + h3.y*u3.y + h3.z*u3.z + h3.w*u3.w;
        #pragma unroll
        for (int o = 16; o > 0; o >>= 1) sc += __shfl_xor_sync(0xffffffffu, sc, o);

        if (sc > m) {                       // warp-uniform branch (sc identical on all lanes)
            float c = __expf(m - sc);       // exp(-inf)=0 handles first iteration
            Z *= c;
            a0.x*=c; a0.y*=c; a0.z*=c; a0.w*=c;
            a1.x*=c; a1.y*=c; a1.z*=c; a1.w*=c;
            a2.x*=c; a2.y*=c; a2.z*=c; a2.w*=c;
            a3.x*=c; a3.y*=c; a3.z*=c; a3.w*=c;
            m = sc;
        }
        float w = __expf(sc - m);
        Z += w;
        a0.x += w*h0.x; a0.y += w*h0.y; a0.z += w*h0.z; a0.w += w*h0.w;
        a1.x += w*h1.x; a1.y += w*h1.y; a1.z += w*h1.z; a1.w += w*h1.w;
        a2.x += w*h2.x; a2.y += w*h2.y; a2.z += w*h2.z; a2.w += w*h2.w;
        a3.x += w*h3.x; a3.y += w*h3.y; a3.z += w*h3.z; a3.w += w*h3.w;
    }

    int split = blockIdx.x * WPB + warp;
    float4* pout = (float4*)(g_part + ((size_t)b * NSPLIT + split) * Hv);
    pout[lane] = a0; pout[lane + 32] = a1; pout[lane + 64] = a2; pout[lane + 96] = a3;
    if (lane == 0) { g_m[b * NSPLIT + split] = m; g_z[b * NSPLIT + split] = Z; }
}

// ---------------------------------------------------------------------------
// Kernel 3: merge warp-splits (rescaled), normalize, concat h_t, tanh GEMV.
// grid=64, block=512. GEMV: 4-way split per output column + smem reduce.
// ---------------------------------------------------------------------------
__global__ void k_out(const float* __restrict__ hid,
                      const float* __restrict__ Wout,
                      float* __restrict__ out) {
    int b = blockIdx.x, tid = threadIdx.x;
    __shared__ float cat[2 * Hv];
    __shared__ float fsh[NSPLIT];
    __shared__ float red[4][Uv];

    // factors f_s = exp(m_s - M); Z = sum f_s * Z_s  (computed by warp 0)
    if (tid < 32) {
        float m0 = g_m[b * NSPLIT + tid], m1 = g_m[b * NSPLIT + 32 + tid];
        float M = fmaxf(m0, m1);
        #pragma unroll
        for (int o = 16; o > 0; o >>= 1) M = fmaxf(M, __shfl_xor_sync(0xffffffffu, M, o));
        float f0 = __expf(m0 - M), f1 = __expf(m1 - M);
        float z = f0 * g_z[b * NSPLIT + tid] + f1 * g_z[b * NSPLIT + 32 + tid];
        #pragma unroll
        for (int o = 16; o > 0; o >>= 1) z += __shfl_xor_sync(0xffffffffu, z, o);
        float invZ = 1.0f / z;
        fsh[tid] = f0 * invZ;
        fsh[tid + 32] = f1 * invZ;
    }
    __syncthreads();

    // combine partial contexts; 512 threads -> one h each
    {
        int h = tid;
        float v = 0.f;
        #pragma unroll 8
        for (int s = 0; s < NSPLIT; s++)
            v += fsh[s] * g_part[((size_t)b * NSPLIT + s) * Hv + h];
        cat[h] = v;
        cat[Hv + h] = hid[((size_t)b * Tv + (Tv - 1)) * Hv + h];
    }
    __syncthreads();

    // GEMV: col = tid % 128, part = tid / 128 covers 256 i's
    int col = tid & (Uv - 1), part = tid >> 7;
    float acc = 0.f;
    const float* wbase = Wout + col;
    int i0 = part * 256;
    #pragma unroll 8
    for (int i = 0; i < 256; i++)
        acc += cat[i0 + i] * wbase[(size_t)(i0 + i) * Uv];
    red[part][col] = acc;
    __syncthreads();
    if (part == 0) {
        float r = red[0][col] + red[1][col] + red[2][col] + red[3][col];
        out[b * Uv + col] = tanhf(r);
    }
}

// ---------------------------------------------------------------------------
extern "C" void kernel_launch(void* const* d_in, const int* in_sizes, int n_in,
                              void* d_out, int out_size) {
    const float* hid  = (const float*)d_in[0];   // (64, 2048, 512)
    const float* Ws   = (const float*)d_in[1];   // (512, 512)
    const float* Wout = (const float*)d_in[2];   // (1024, 128)
    float* out = (float*)d_out;                  // (64, 128)

    dim3 gu(16, Bv);
    k_u<<<gu, 128>>>(hid, Ws);
    dim3 gf(NBLK, Bv);
    k_fused<<<gf, 256>>>(hid);
    k_out<<<Bv, 512>>>(hid, Wout, out);
}

// round 7
// speedup vs baseline: 1.9727x; 1.0987x over previous
#include <cuda_runtime.h>
#include <math.h>

#define Bv 64
#define Tv 2048
#define Hv 512
#define Uv 128
#define NBLK 8                 // fused blocks per batch
#define WPB 8                  // warps per fused block
#define NSPLIT (NBLK * WPB)    // 64 warp-splits per batch
#define ROWS_PER_WARP (Tv / NSPLIT)  // 32

// scratch (allocation-free rule: __device__ globals)
__device__ float g_u[Bv * Hv];                   // W_score @ h_t
__device__ float g_part[Bv * NSPLIT * Hv];       // per-warp unnormalized contexts
__device__ float g_m[Bv * NSPLIT];               // per-warp running max
__device__ float g_z[Bv * NSPLIT];               // per-warp exp-sum

// ---------------------------------------------------------------------------
// Kernel 1: u[b,h] = sum_k W_score[h,k] * h_t[b,k]
// grid=(64, B) = 4096 blocks, block=128 (4 warps x 2 rows each) -> one
// latency epoch deep, maximum parallelism.
// ---------------------------------------------------------------------------
__global__ void k_u(const float* __restrict__ hid, const float* __restrict__ Ws) {
    int b = blockIdx.y, seg = blockIdx.x, tid = threadIdx.x;
    __shared__ float4 sh[Hv / 4];
    const float4* htrow = (const float4*)(hid + ((size_t)b * Tv + (Tv - 1)) * Hv);
    sh[tid] = htrow[tid];
    __syncthreads();

    int warp = tid >> 5, lane = tid & 31;
    float4 hv0 = sh[lane], hv1 = sh[lane + 32], hv2 = sh[lane + 64], hv3 = sh[lane + 96];

    #pragma unroll
    for (int i = 0; i < 2; i++) {
        int h = seg * 8 + warp * 2 + i;
        const float4* wrow = (const float4*)(Ws + (size_t)h * Hv);
        float4 w0 = wrow[lane], w1 = wrow[lane + 32], w2 = wrow[lane + 64], w3 = wrow[lane + 96];
        float s = w0.x*hv0.x + w0.y*hv0.y + w0.z*hv0.z + w0.w*hv0.w
                + w1.x*hv1.x + w1.y*hv1.y + w1.z*hv1.z + w1.w*hv1.w
                + w2.x*hv2.x + w2.y*hv2.y + w2.z*hv2.z + w2.w*hv2.w
                + w3.x*hv3.x + w3.y*hv3.y + w3.z*hv3.z + w3.w*hv3.w;
        #pragma unroll
        for (int o = 16; o > 0; o >>= 1) s += __shfl_xor_sync(0xffffffffu, s, o);
        if (lane == 0) g_u[b * Hv + h] = s;
    }
}

// ---------------------------------------------------------------------------
// Kernel 2: single-pass warp-local online softmax + context accumulation.
// Two rows per iteration: overlapped shuffle chains, half the max-update
// frequency. grid=(NBLK, B)=512 blocks, block=256 (8 warps).
// ---------------------------------------------------------------------------
__global__ void __launch_bounds__(256) k_fused(const float* __restrict__ hid) {
    int b = blockIdx.y, tid = threadIdx.x;
    int warp = tid >> 5, lane = tid & 31;
    __shared__ float4 su[Hv / 4];
    if (tid < Hv / 4) su[tid] = ((const float4*)(g_u + b * Hv))[tid];
    __syncthreads();

    float4 u0 = su[lane], u1 = su[lane + 32], u2 = su[lane + 64], u3 = su[lane + 96];

    int t0 = blockIdx.x * (WPB * ROWS_PER_WARP) + warp * ROWS_PER_WARP;
    const float4* base = (const float4*)(hid + ((size_t)b * Tv + t0) * Hv);

    float m = -INFINITY, Z = 0.f;
    float4 a0 = make_float4(0.f,0.f,0.f,0.f), a1 = a0, a2 = a0, a3 = a0;

    #pragma unroll 2
    for (int t = 0; t < ROWS_PER_WARP; t += 2) {
        const float4* rA = base + (size_t)t * (Hv / 4);
        const float4* rB = rA + (Hv / 4);
        float4 p0 = rA[lane], p1 = rA[lane + 32], p2 = rA[lane + 64], p3 = rA[lane + 96];
        float4 q0 = rB[lane], q1 = rB[lane + 32], q2 = rB[lane + 64], q3 = rB[lane + 96];

        float s0 = p0.x*u0.x + p0.y*u0.y + p0.z*u0.z + p0.w*u0.w
                 + p1.x*u1.x + p1.y*u1.y + p1.z*u1.z + p1.w*u1.w
                 + p2.x*u2.x + p2.y*u2.y + p2.z*u2.z + p2.w*u2.w
                 + p3.x*u3.x + p3.y*u3.y + p3.z*u3.z + p3.w*u3.w;
        float s1 = q0.x*u0.x + q0.y*u0.y + q0.z*u0.z + q0.w*u0.w
                 + q1.x*u1.x + q1.y*u1.y + q1.z*u1.z + q1.w*u1.w
                 + q2.x*u2.x + q2.y*u2.y + q2.z*u2.z + q2.w*u2.w
                 + q3.x*u3.x + q3.y*u3.y + q3.z*u3.z + q3.w*u3.w;
        #pragma unroll
        for (int o = 16; o > 0; o >>= 1) {
            s0 += __shfl_xor_sync(0xffffffffu, s0, o);
            s1 += __shfl_xor_sync(0xffffffffu, s1, o);
        }

        float mp = fmaxf(s0, s1);
        if (mp > m) {                       // warp-uniform, rare
            float c = __expf(m - mp);       // exp(-inf)=0 covers first iteration
            Z *= c;
            a0.x*=c; a0.y*=c; a0.z*=c; a0.w*=c;
            a1.x*=c; a1.y*=c; a1.z*=c; a1.w*=c;
            a2.x*=c; a2.y*=c; a2.z*=c; a2.w*=c;
            a3.x*=c; a3.y*=c; a3.z*=c; a3.w*=c;
            m = mp;
        }
        float w0 = __expf(s0 - m), w1 = __expf(s1 - m);
        Z += w0 + w1;
        a0.x += w0*p0.x + w1*q0.x; a0.y += w0*p0.y + w1*q0.y;
        a0.z += w0*p0.z + w1*q0.z; a0.w += w0*p0.w + w1*q0.w;
        a1.x += w0*p1.x + w1*q1.x; a1.y += w0*p1.y + w1*q1.y;
        a1.z += w0*p1.z + w1*q1.z; a1.w += w0*p1.w + w1*q1.w;
        a2.x += w0*p2.x + w1*q2.x; a2.y += w0*p2.y + w1*q2.y;
        a2.z += w0*p2.z + w1*q2.z; a2.w += w0*p2.w + w1*q2.w;
        a3.x += w0*p3.x + w1*q3.x; a3.y += w0*p3.y + w1*q3.y;
        a3.z += w0*p3.z + w1*q3.z; a3.w += w0*p3.w + w1*q3.w;
    }

    int split = blockIdx.x * WPB + warp;
    float4* pout = (float4*)(g_part + ((size_t)b * NSPLIT + split) * Hv);
    pout[lane] = a0; pout[lane + 32] = a1; pout[lane + 64] = a2; pout[lane + 96] = a3;
    if (lane == 0) { g_m[b * NSPLIT + split] = m; g_z[b * NSPLIT + split] = Z; }
}

// ---------------------------------------------------------------------------
// Kernel 3: merge warp-splits (rescaled), normalize, concat h_t, tanh GEMV.
// grid=64, block=512. GEMV: 4-way split per output column + smem reduce.
// ---------------------------------------------------------------------------
__global__ void k_out(const float* __restrict__ hid,
                      const float* __restrict__ Wout,
                      float* __restrict__ out) {
    int b = blockIdx.x, tid = threadIdx.x;
    __shared__ float cat[2 * Hv];
    __shared__ float fsh[NSPLIT];
    __shared__ float red[4][Uv];

    // factors f_s = exp(m_s - M); Z = sum f_s * Z_s  (computed by warp 0)
    if (tid < 32) {
        float m0 = g_m[b * NSPLIT + tid], m1 = g_m[b * NSPLIT + 32 + tid];
        float M = fmaxf(m0, m1);
        #pragma unroll
        for (int o = 16; o > 0; o >>= 1) M = fmaxf(M, __shfl_xor_sync(0xffffffffu, M, o));
        float f0 = __expf(m0 - M), f1 = __expf(m1 - M);
        float z = f0 * g_z[b * NSPLIT + tid] + f1 * g_z[b * NSPLIT + 32 + tid];
        #pragma unroll
        for (int o = 16; o > 0; o >>= 1) z += __shfl_xor_sync(0xffffffffu, z, o);
        float invZ = 1.0f / z;
        fsh[tid] = f0 * invZ;
        fsh[tid + 32] = f1 * invZ;
    }
    __syncthreads();

    // combine partial contexts; 512 threads -> one h each
    {
        int h = tid;
        float v = 0.f;
        #pragma unroll 8
        for (int s = 0; s < NSPLIT; s++)
            v += fsh[s] * g_part[((size_t)b * NSPLIT + s) * Hv + h];
        cat[h] = v;
        cat[Hv + h] = hid[((size_t)b * Tv + (Tv - 1)) * Hv + h];
    }
    __syncthreads();

    // GEMV: col = tid % 128, part = tid / 128 covers 256 i's
    int col = tid & (Uv - 1), part = tid >> 7;
    float acc = 0.f;
    const float* wbase = Wout + col;
    int i0 = part * 256;
    #pragma unroll 8
    for (int i = 0; i < 256; i++)
        acc += cat[i0 + i] * wbase[(size_t)(i0 + i) * Uv];
    red[part][col] = acc;
    __syncthreads();
    if (part == 0) {
        float r = red[0][col] + red[1][col] + red[2][col] + red[3][col];
        out[b * Uv + col] = tanhf(r);
    }
}

// ---------------------------------------------------------------------------
extern "C" void kernel_launch(void* const* d_in, const int* in_sizes, int n_in,
                              void* d_out, int out_size) {
    const float* hid  = (const float*)d_in[0];   // (64, 2048, 512)
    const float* Ws   = (const float*)d_in[1];   // (512, 512)
    const float* Wout = (const float*)d_in[2];   // (1024, 128)
    float* out = (float*)d_out;                  // (64, 128)

    dim3 gu(64, Bv);
    k_u<<<gu, 128>>>(hid, Ws);
    dim3 gf(NBLK, Bv);
    k_fused<<<gf, 256>>>(hid);
    k_out<<<Bv, 512>>>(hid, Wout, out);
}